// round 12
// baseline (speedup 1.0000x reference)
#include <cuda_runtime.h>
#include <cstdint>

// TokenBladeBank: FNV-1a 4-gram hash -> gather from 8 blade banks.
// token_window: (8, 8192, 4) int32 OR int64 (detected in-warp)
// bank:         (8, 500000, 16) float32
// out:          (8, 8192, 8, 16) float32  ->  out[pos*128 + blade*16 + d]
//
// R10 (12.7us) with stores switched __stcs -> __stwt (write-through).
// Rationale: bench runs warm (graph replays identical addresses; L2 not
// flushed per launch) and the ~31MB hot bank set should stay L2-resident,
// but evict-first stores still ALLOCATE 32MB of dirty L2 lines per replay,
// evicting part of the warm set. Write-through sends the never-read-again
// output straight toward DRAM without displacing L2 residency.
// Gather structure unchanged (local optimum): 8 pos/warp, width-8
// shuffle-shared hashing, 8 independent float4 __ldg gathers (each 64B row
// covered by 4 lanes = 2 full sectors), 128-thread blocks, grid 2048.

#define TBB_N_SLOTS    500000u
#define TBB_FNV_OFFSET 2166136261u
#define TBB_FNV_PRIME  16777619u
#define TBB_POS_PER_WARP 8

__device__ __forceinline__ unsigned tbb_fnv4(unsigned a, unsigned b,
                                             unsigned c, unsigned d)
{
    unsigned h = TBB_FNV_OFFSET;
    h = (h ^ a) * TBB_FNV_PRIME;
    h = (h ^ b) * TBB_FNV_PRIME;
    h = (h ^ c) * TBB_FNV_PRIME;
    h = (h ^ d) * TBB_FNV_PRIME;
    return h % TBB_N_SLOTS;
}

__global__ void __launch_bounds__(128)
tbb_gather_kernel(const unsigned* __restrict__ tw,
                  const float4*  __restrict__ bank,
                  float4*        __restrict__ out,
                  int n_pos)
{
    const int t    = blockIdx.x * blockDim.x + threadIdx.x;
    const int warp = t >> 5;
    const int lane = t & 31;
    const int pos0 = warp * TBB_POS_PER_WARP;
    if (pos0 >= n_pos) return;

    // In-warp dtype detection: odd 32-bit words of the first 64 token words.
    // int64 little-endian layout => all are zero high-halves (tokens < 50257);
    // int32 layout => random tokens, P(all 32 == 0) ~ 50257^-32 ~ 0.
    const unsigned probe = __ldg(&tw[2 * lane + 1]);
    const unsigned nz    = __ballot_sync(0xffffffffu, probe != 0u);
    const int stride     = (nz == 0u) ? 2 : 1;

    const unsigned blade = (unsigned)lane >> 2;   // 0..7
    const unsigned q     = (unsigned)lane & 3;    // float4 within 16-fp row
    const int      sub   = lane & 7;              // which position I hash

    const uint4* tw4 = (const uint4*)tw;

    // Each lane hashes ONE position (pos0+sub); width-8 shuffles broadcast
    // all 8 addresses to every lane.
    unsigned myaddr;
    if (stride == 1) {
        uint4 tk = __ldg(&tw4[pos0 + sub]);
        myaddr = tbb_fnv4(tk.x, tk.y, tk.z, tk.w);
    } else {
        const size_t p = (size_t)(pos0 + sub) * 2;
        uint4 ta = __ldg(&tw4[p]);
        uint4 tb = __ldg(&tw4[p + 1]);
        myaddr = tbb_fnv4(ta.x, ta.z, tb.x, tb.z);
    }

    unsigned addr[TBB_POS_PER_WARP];
    #pragma unroll
    for (int g = 0; g < TBB_POS_PER_WARP; g++)
        addr[g] = __shfl_sync(0xffffffffu, myaddr, g, 8);

    // 8 independent random 16 B gathers (MLP=8).
    // Lanes 4b..4b+3 cover one contiguous 64 B row: perfect sector use.
    float4 v[TBB_POS_PER_WARP];
    #pragma unroll
    for (int g = 0; g < TBB_POS_PER_WARP; g++) {
        const size_t bidx =
            ((size_t)blade * TBB_N_SLOTS + (size_t)addr[g]) * 4 + q;
        v[g] = __ldg(&bank[bidx]);
    }

    // 8 coalesced 512 B write-through stores -> 4 KB contiguous per warp,
    // without allocating dirty L2 lines that evict the warm bank set.
    #pragma unroll
    for (int g = 0; g < TBB_POS_PER_WARP; g++)
        __stwt(&out[(size_t)(pos0 + g) * 32 + lane], v[g]);
}

extern "C" void kernel_launch(void* const* d_in, const int* in_sizes, int n_in,
                              void* d_out, int out_size)
{
    const unsigned* tw   = (const unsigned*)d_in[0];
    const float4*   bank = (const float4*)d_in[1];
    float4*         out  = (float4*)d_out;

    const int n_pos = out_size / 128;             // 65536 positions (dtype-proof)

    const int threads = 128;
    const int warps   = (n_pos + TBB_POS_PER_WARP - 1) / TBB_POS_PER_WARP;
    const int blocks  = (warps * 32 + threads - 1) / threads;  // 2048
    tbb_gather_kernel<<<blocks, threads>>>(tw, bank, out, n_pos);
}